// round 16
// baseline (speedup 1.0000x reference)
#include <cuda_runtime.h>
#include <math.h>
#include <stdint.h>

#define BATCH 2
#define SEQ 2048
#define DMODEL 1024
#define HEADS 16
#define DK 64
#define NROWS (BATCH*HEADS*SEQ)

// tf32-rounded copies of inputs
static __device__ float g_cq[BATCH*SEQ*DMODEL];
static __device__ float g_ck[BATCH*SEQ*DMODEL];
static __device__ float g_cv[BATCH*SEQ*DMODEL];
static __device__ float g_cwq[DMODEL*DMODEL];
static __device__ float g_cwk[DMODEL*DMODEL];
static __device__ float g_cwv[DMODEL*DMODEL];
static __device__ float g_cwo[DMODEL*DMODEL];
// Projected scratch (tf32-rounded), [B,S,D] layout
static __device__ float g_q[BATCH*SEQ*DMODEL];
static __device__ float g_k[BATCH*SEQ*DMODEL];
static __device__ float g_v[BATCH*SEQ*DMODEL];
static __device__ float g_ctx[BATCH*SEQ*DMODEL];
// per-row 1/sum
static __device__ float g_inv[NROWS];

__device__ __forceinline__ float to_tf32(float x) {
    float y;
    asm("cvt.rna.tf32.f32 %0, %1;" : "=f"(y) : "f"(x));
    return y;
}
// exp(x/8) = 2^(x * 0.125*log2(e))
__device__ __forceinline__ float exp8(float x) {
    float y;
    asm("ex2.approx.ftz.f32 %0, %1;" : "=f"(y) : "f"(x * 0.18033688011112042f));
    return y;
}
__device__ __forceinline__ void mma8(float* d, const uint32_t* a, const uint32_t* b) {
    asm volatile(
        "mma.sync.aligned.m16n8k8.row.col.f32.tf32.tf32.f32 "
        "{%0,%1,%2,%3}, {%4,%5,%6,%7}, {%8,%9}, {%0,%1,%2,%3};\n"
        : "+f"(d[0]), "+f"(d[1]), "+f"(d[2]), "+f"(d[3])
        : "r"(a[0]), "r"(a[1]), "r"(a[2]), "r"(a[3]),
          "r"(b[0]), "r"(b[1]));
}
__device__ __forceinline__ void cp16(uint32_t dst_smem, const void* src) {
    asm volatile("cp.async.cg.shared.global [%0], [%1], 16;\n" :: "r"(dst_smem), "l"(src));
}
__device__ __forceinline__ void cp_commit() { asm volatile("cp.async.commit_group;\n"); }
template<int N> __device__ __forceinline__ void cp_wait() {
    asm volatile("cp.async.wait_group %0;\n" :: "n"(N));
}
// streaming store (evict-first): probs is write-once, never re-read
__device__ __forceinline__ void stg_cs2(float* p, float a, float b) {
    asm volatile("st.global.cs.v2.f32 [%0], {%1,%2};" :: "l"(p), "f"(a), "f"(b) : "memory");
}

// ---------------------------------------------------------------------------
__global__ void __launch_bounds__(256)
cvt_pass(const float* s0, float* d0, int n0,
         const float* s1, float* d1, int n1,
         const float* s2, float* d2, int n2,
         const float* s3, float* d3, int n3)
{
    const int z = blockIdx.y;
    const float* s = (z==0)?s0:((z==1)?s1:((z==2)?s2:s3));
    float*       d = (z==0)?d0:((z==1)?d1:((z==2)?d2:d3));
    const int    n = (z==0)?n0:((z==1)?n1:((z==2)?n2:n3));
    for (int i = blockIdx.x*256 + threadIdx.x; i < n; i += gridDim.x*256) {
        float4 x = ((const float4*)s)[i];
        x.x = to_tf32(x.x); x.y = to_tf32(x.y);
        x.z = to_tf32(x.z); x.w = to_tf32(x.w);
        ((float4*)d)[i] = x;
    }
}

// ---------------------------------------------------------------------------
// Projection GEMM: C[4096,1024] = A @ W^T + bias, z selects triple.
// ---------------------------------------------------------------------------
template<bool CVT_OUT>
__global__ void __launch_bounds__(256, 2)
proj_gemm(const float* __restrict__ A0, const float* __restrict__ A1, const float* __restrict__ A2,
          const float* __restrict__ W0, const float* __restrict__ W1, const float* __restrict__ W2,
          const float* __restrict__ B0, const float* __restrict__ B1, const float* __restrict__ B2,
          float* __restrict__ C0, float* __restrict__ C1, float* __restrict__ C2)
{
    extern __shared__ __align__(16) float sm[];
    const int tid = threadIdx.x;
    const int z = blockIdx.z;
    const float* A    = (z==0) ? A0 : ((z==1) ? A1 : A2);
    const float* W    = (z==0) ? W0 : ((z==1) ? W1 : W2);
    const float* bias = (z==0) ? B0 : ((z==1) ? B1 : B2);
    float*       C    = (z==0) ? C0 : ((z==1) ? C1 : C2);
    const int tileN = blockIdx.x * 128;
    const int tileM = blockIdx.y * 128;

    const int warp = tid >> 5, lane = tid & 31, gid = lane >> 2, tig = lane & 3;
    const int wM = (warp & 1) * 64, wN = (warp >> 1) * 32;
    const uint32_t smb = (uint32_t)__cvta_generic_to_shared(sm);

    float acc[4][4][4];
    #pragma unroll
    for (int i=0;i<4;++i)
        #pragma unroll
        for (int j=0;j<4;++j)
            #pragma unroll
            for (int r=0;r<4;++r) acc[i][j][r]=0.f;

    #pragma unroll
    for (int i=0;i<4;++i) {
        int e = tid + i*256, m = e>>3, kq = e&7;
        cp16(smb + (uint32_t)((m*36 + kq*4)*4),          A + (size_t)(tileM+m)*1024 + kq*4);
        cp16(smb + (uint32_t)((9216 + m*36 + kq*4)*4),   W + (size_t)(tileN+m)*1024 + kq*4);
    }
    cp_commit();

    for (int it = 0; it < 32; ++it) {
        const int cur = it & 1;
        if (it < 31) {
            const int nb = cur ^ 1;
            const int k0 = (it+1)*32;
            #pragma unroll
            for (int i=0;i<4;++i) {
                int e = tid + i*256, m = e>>3, kq = e&7;
                cp16(smb + (uint32_t)((nb*4608 + m*36 + kq*4)*4),        A + (size_t)(tileM+m)*1024 + k0 + kq*4);
                cp16(smb + (uint32_t)((9216 + nb*4608 + m*36 + kq*4)*4), W + (size_t)(tileN+m)*1024 + k0 + kq*4);
            }
            cp_commit();
            cp_wait<1>();
        } else {
            cp_wait<0>();
        }
        __syncthreads();

        const float* As = sm + cur*4608;
        const float* Ws = sm + 9216 + cur*4608;
        #pragma unroll
        for (int ks = 0; ks < 32; ks += 8) {
            uint32_t af[4][4], bf[4][2];
            #pragma unroll
            for (int mi=0;mi<4;++mi) {
                const int m0 = wM + mi*16;
                af[mi][0] = __float_as_uint(As[(m0+gid  )*36 + ks+tig  ]);
                af[mi][1] = __float_as_uint(As[(m0+gid+8)*36 + ks+tig  ]);
                af[mi][2] = __float_as_uint(As[(m0+gid  )*36 + ks+tig+4]);
                af[mi][3] = __float_as_uint(As[(m0+gid+8)*36 + ks+tig+4]);
            }
            #pragma unroll
            for (int ni=0;ni<4;++ni) {
                const int n0 = wN + ni*8;
                bf[ni][0] = __float_as_uint(Ws[(n0+gid)*36 + ks+tig  ]);
                bf[ni][1] = __float_as_uint(Ws[(n0+gid)*36 + ks+tig+4]);
            }
            #pragma unroll
            for (int mi=0;mi<4;++mi)
                #pragma unroll
                for (int ni=0;ni<4;++ni)
                    mma8(acc[mi][ni], af[mi], bf[ni]);
        }
        __syncthreads();
    }

    #pragma unroll
    for (int mi=0;mi<4;++mi) {
        const int r0 = tileM + wM + mi*16 + gid;
        #pragma unroll
        for (int ni=0;ni<4;++ni) {
            const int c0 = tileN + wN + ni*8 + tig*2;
            const float b0 = bias[c0], b1 = bias[c0+1];
            float v0 = acc[mi][ni][0]+b0, v1 = acc[mi][ni][1]+b1;
            float v2 = acc[mi][ni][2]+b0, v3 = acc[mi][ni][3]+b1;
            if (CVT_OUT) {
                v0 = to_tf32(v0); v1 = to_tf32(v1);
                v2 = to_tf32(v2); v3 = to_tf32(v3);
            }
            *(float2*)(C + (size_t)r0*1024 + c0)     = make_float2(v0, v1);
            *(float2*)(C + (size_t)(r0+8)*1024 + c0) = make_float2(v2, v3);
        }
    }
}

// ---------------------------------------------------------------------------
// Flash forward (R14, unchanged): warp-specialized producer/consumer.
// ---------------------------------------------------------------------------
__global__ void __launch_bounds__(256, 1)
flash_fwd(const float* __restrict__ q, const float* __restrict__ kmat,
          const float* __restrict__ v, float* __restrict__ ginv,
          float* __restrict__ ctx)
{
    extern __shared__ __align__(16) float sm[];
    float* Qs   = sm;
    float* redf = sm + 44032;
    float* smi  = sm + 44288;

    const int tid = threadIdx.x, rowtile = blockIdx.x, z = blockIdx.y;
    const int b = z >> 4, h = z & 15;
    const float* Qp = q    + ((size_t)b*SEQ + rowtile*128)*DMODEL + h*DK;
    const float* Kp = kmat + (size_t)b*SEQ*DMODEL + h*DK;
    const float* Vp = v    + (size_t)b*SEQ*DMODEL + h*DK;
    const uint32_t smb = (uint32_t)__cvta_generic_to_shared(sm);

    const int warp = tid >> 5, lane = tid & 31, gid = lane >> 2, tig = lane & 3;
    const bool isA = (warp < 4);
    const int wMa = (warp & 1) * 64, wNa = ((warp >> 1) & 1) * 32;
    const int warp_na = (warp >> 1) & 1;
    const int wl = warp & 3;
    const int wMb = (wl & 1) * 64, wNb = (wl >> 1) * 32;

    // prologue: Q (8 f4/thread) + K(0) (4 f4/thread)
    #pragma unroll
    for (int i=0;i<8;++i) {
        int e = tid + i*256, m = e>>4, kq = e&15;
        cp16(smb + (uint32_t)((m*68 + kq*4)*4), Qp + (size_t)m*1024 + kq*4);
    }
    #pragma unroll
    for (int i=0;i<4;++i) {
        int e = tid + i*256, m = e>>4, kq = e&15;
        cp16(smb + (uint32_t)((8704 + m*68 + kq*4)*4), Kp + (size_t)m*1024 + kq*4);
    }
    cp_commit();

    float acc2[4][4][4];   // B ctx accumulator
    #pragma unroll
    for (int i=0;i<4;++i)
        #pragma unroll
        for (int j=0;j<4;++j)
            #pragma unroll
            for (int r=0;r<4;++r) acc2[i][j][r]=0.f;
    float srun[4][2];      // A per-thread row-sum partials
    #pragma unroll
    for (int mi=0;mi<4;++mi) { srun[mi][0]=0.f; srun[mi][1]=0.f; }

    for (int nt = 0; nt < 32; ++nt) {
        const int cur = nt & 1;
        cp_wait<0>();
        __syncthreads();   // K(nt), V(nt-1) landed; Es stable

        // prefetch K(nt+1) -> Ks[nt+1&1], V(nt) -> Vs[nt&1]
        {
            #pragma unroll
            for (int i=0;i<4;++i) {
                int e = tid + i*256, m = e>>4, kq = e&15;
                if (nt < 31)
                    cp16(smb + (uint32_t)((8704 + (cur^1)*4352 + m*68 + kq*4)*4),
                         Kp + (size_t)((nt+1)*64+m)*1024 + kq*4);
                cp16(smb + (uint32_t)((17408 + cur*4608 + m*72 + kq*4)*4),
                     Vp + (size_t)(nt*64+m)*1024 + kq*4);
            }
            cp_commit();
        }

        if (isA) {
            // scores mma: 128x64x64
            const float* Kb = sm + 8704 + cur*4352;
            float acc[4][4][4];
            #pragma unroll
            for (int i=0;i<4;++i)
                #pragma unroll
                for (int j=0;j<4;++j)
                    #pragma unroll
                    for (int r=0;r<4;++r) acc[i][j][r]=0.f;
            #pragma unroll
            for (int ks = 0; ks < 64; ks += 8) {
                uint32_t af[4][4], bf[4][2];
                #pragma unroll
                for (int mi=0;mi<4;++mi) {
                    const int m0 = wMa + mi*16;
                    af[mi][0] = __float_as_uint(Qs[(m0+gid  )*68 + ks+tig  ]);
                    af[mi][1] = __float_as_uint(Qs[(m0+gid+8)*68 + ks+tig  ]);
                    af[mi][2] = __float_as_uint(Qs[(m0+gid  )*68 + ks+tig+4]);
                    af[mi][3] = __float_as_uint(Qs[(m0+gid+8)*68 + ks+tig+4]);
                }
                #pragma unroll
                for (int ni=0;ni<4;++ni) {
                    const int n0 = wNa + ni*8;
                    bf[ni][0] = __float_as_uint(Kb[(n0+gid)*68 + ks+tig  ]);
                    bf[ni][1] = __float_as_uint(Kb[(n0+gid)*68 + ks+tig+4]);
                }
                #pragma unroll
                for (int mi=0;mi<4;++mi)
                    #pragma unroll
                    for (int ni=0;ni<4;++ni)
                        mma8(acc[mi][ni], af[mi], bf[ni]);
            }

            // e = tf32(exp8(s)); per-thread partial sums (no shfl in loop)
            #pragma unroll
            for (int mi=0;mi<4;++mi) {
                #pragma unroll
                for (int hf=0;hf<2;++hf) {
                    float s = 0.f;
                    #pragma unroll
                    for (int ni=0;ni<4;++ni) {
                        float e0 = to_tf32(exp8(acc[mi][ni][hf*2]));
                        float e1 = to_tf32(exp8(acc[mi][ni][hf*2+1]));
                        acc[mi][ni][hf*2]   = e0;
                        acc[mi][ni][hf*2+1] = e1;
                        s += e0 + e1;
                    }
                    srun[mi][hf] += s;
                }
            }
            float* Eb = sm + 26624 + cur*8704;
            #pragma unroll
            for (int mi=0;mi<4;++mi) {
                const int r0 = wMa + mi*16 + gid;
                #pragma unroll
                for (int ni=0;ni<4;++ni) {
                    const int c0 = wNa + ni*8 + tig*2;
                    *(float2*)(Eb + (r0  )*68 + c0) = make_float2(acc[mi][ni][0], acc[mi][ni][1]);
                    *(float2*)(Eb + (r0+8)*68 + c0) = make_float2(acc[mi][ni][2], acc[mi][ni][3]);
                }
            }
        } else if (nt > 0) {
            // ctx mma: acc2 += Es[(nt-1)&1] @ Vs[(nt-1)&1]
            const float* Eb = sm + 26624 + (cur^1)*8704;
            const float* Vb = sm + 17408 + (cur^1)*4608;
            #pragma unroll
            for (int ks = 0; ks < 64; ks += 8) {
                uint32_t af[4][4], bf[4][2];
                #pragma unroll
                for (int mi=0;mi<4;++mi) {
                    const int m0 = wMb + mi*16;
                    af[mi][0] = __float_as_uint(Eb[(m0+gid  )*68 + ks+tig  ]);
                    af[mi][1] = __float_as_uint(Eb[(m0+gid+8)*68 + ks+tig  ]);
                    af[mi][2] = __float_as_uint(Eb[(m0+gid  )*68 + ks+tig+4]);
                    af[mi][3] = __float_as_uint(Eb[(m0+gid+8)*68 + ks+tig+4]);
                }
                #pragma unroll
                for (int ni=0;ni<4;++ni) {
                    const int n0 = wNb + ni*8;
                    bf[ni][0] = __float_as_uint(Vb[(ks+tig  )*72 + n0+gid]);
                    bf[ni][1] = __float_as_uint(Vb[(ks+tig+4)*72 + n0+gid]);
                }
                #pragma unroll
                for (int mi=0;mi<4;++mi)
                    #pragma unroll
                    for (int ni=0;ni<4;++ni)
                        mma8(acc2[mi][ni], af[mi], bf[ni]);
            }
        }
        __syncthreads();
    }

    // tail: B processes tile 31; A reduces (deferred shuffles) + publishes sums
    cp_wait<0>();
    __syncthreads();
    if (isA) {
        #pragma unroll
        for (int mi=0;mi<4;++mi) {
            #pragma unroll
            for (int hf=0;hf<2;++hf) {
                float s = srun[mi][hf];
                s += __shfl_xor_sync(0xffffffffu, s, 1);
                s += __shfl_xor_sync(0xffffffffu, s, 2);
                if (tig == 0)
                    redf[warp_na*128 + wMa + mi*16 + gid + hf*8] = s;
            }
        }
    } else {
        const float* Eb = sm + 26624 + 1*8704;   // Es[31&1]
        const float* Vb = sm + 17408 + 1*4608;   // Vs[31&1]
        #pragma unroll
        for (int ks = 0; ks < 64; ks += 8) {
            uint32_t af[4][4], bf[4][2];
            #pragma unroll
            for (int mi=0;mi<4;++mi) {
                const int m0 = wMb + mi*16;
                af[mi][0] = __float_as_uint(Eb[(m0+gid  )*68 + ks+tig  ]);
                af[mi][1] = __float_as_uint(Eb[(m0+gid+8)*68 + ks+tig  ]);
                af[mi][2] = __float_as_uint(Eb[(m0+gid  )*68 + ks+tig+4]);
                af[mi][3] = __float_as_uint(Eb[(m0+gid+8)*68 + ks+tig+4]);
            }
            #pragma unroll
            for (int ni=0;ni<4;++ni) {
                const int n0 = wNb + ni*8;
                bf[ni][0] = __float_as_uint(Vb[(ks+tig  )*72 + n0+gid]);
                bf[ni][1] = __float_as_uint(Vb[(ks+tig+4)*72 + n0+gid]);
            }
            #pragma unroll
            for (int mi=0;mi<4;++mi)
                #pragma unroll
                for (int ni=0;ni<4;++ni)
                    mma8(acc2[mi][ni], af[mi], bf[ni]);
        }
    }
    __syncthreads();
    if (tid < 128) {
        float S = redf[tid] + redf[128+tid];
        float iv = 1.f / S;
        smi[tid] = iv;
        ginv[(size_t)z*SEQ + rowtile*128 + tid] = iv;
    }
    __syncthreads();

    // B epilogue: scale by inv[row], write ctx
    if (!isA) {
        float* Cp = ctx + ((size_t)b*SEQ + rowtile*128)*DMODEL + h*DK;
        #pragma unroll
        for (int mi=0;mi<4;++mi) {
            const int r0 = wMb + mi*16 + gid;
            const float iv0 = smi[r0], iv1 = smi[r0+8];
            #pragma unroll
            for (int ni=0;ni<4;++ni) {
                const int c0 = wNb + ni*8 + tig*2;
                *(float2*)(Cp + (size_t)r0*1024 + c0)
                    = make_float2(to_tf32(acc2[mi][ni][0]*iv0), to_tf32(acc2[mi][ni][1]*iv0));
                *(float2*)(Cp + (size_t)(r0+8)*1024 + c0)
                    = make_float2(to_tf32(acc2[mi][ni][2]*iv1), to_tf32(acc2[mi][ni][3]*iv1));
            }
        }
    }
}

// ---------------------------------------------------------------------------
// Probs writer v2: per CTA 128 rows x 256 cols (2 ntiles), K double-buffered,
// streaming (.cs) stores. p = exp8(s) * inv[row].
// smem (words): Qs[128][68]=0, Ks[2][128][68]=8704, smi[128]=26112.
// Total 26240 w = 104960 B -> occ 2.
// ---------------------------------------------------------------------------
__global__ void __launch_bounds__(256, 2)
probs_write(const float* __restrict__ q, const float* __restrict__ kmat,
            const float* __restrict__ ginv, float* __restrict__ probs)
{
    extern __shared__ __align__(16) float sm[];
    float* smi = sm + 26112;
    const int tid = threadIdx.x;
    const int ntile2 = blockIdx.x, rowtile = blockIdx.y, z = blockIdx.z;
    const int b = z >> 4, h = z & 15;

    const float* Qp = q    + ((size_t)b*SEQ + rowtile*128)*DMODEL + h*DK;
    const float* Kp = kmat + ((size_t)b*SEQ + ntile2*256)*DMODEL + h*DK;
    const uint32_t smb = (uint32_t)__cvta_generic_to_shared(sm);

    // prologue: Q + K tile 0
    #pragma unroll
    for (int i=0;i<8;++i) {
        int e = tid + i*256, m = e>>4, kq = e&15;
        cp16(smb + (uint32_t)((m*68 + kq*4)*4),          Qp + (size_t)m*1024 + kq*4);
        cp16(smb + (uint32_t)((8704 + m*68 + kq*4)*4),   Kp + (size_t)m*1024 + kq*4);
    }
    cp_commit();
    if (tid < 128) smi[tid] = ginv[(size_t)z*SEQ + rowtile*128 + tid];

    const int warp = tid >> 5, lane = tid & 31, gid = lane >> 2, tig = lane & 3;
    const int wM = (warp & 1) * 64, wN = (warp >> 1) * 32;
    const float* Qs = sm;
    float* Cp = probs + (size_t)z*SEQ*SEQ;

    for (int j = 0; j < 2; ++j) {
        cp_wait<0>();
        __syncthreads();

        if (j == 0) {   // prefetch K tile 1 (overlaps tile-0 mma + stores)
            #pragma unroll
            for (int i=0;i<8;++i) {
                int e = tid + i*256, m = e>>4, kq = e&15;
                cp16(smb + (uint32_t)((8704 + 8704 + m*68 + kq*4)*4),
                     Kp + (size_t)(128+m)*1024 + kq*4);
            }
            cp_commit();
        }

        const float* Ks = sm + 8704 + j*8704;
        float acc[4][4][4];
        #pragma unroll
        for (int i=0;i<4;++i)
            #pragma unroll
            for (int jj=0;jj<4;++jj)
                #pragma unroll
                for (int r=0;r<4;++r) acc[i][jj][r]=0.f;

        #pragma unroll
        for (int ks = 0; ks < 64; ks += 8) {
            uint32_t af[4][4], bf[4][2];
            #pragma unroll
            for (int mi=0;mi<4;++mi) {
                const int m0 = wM + mi*16;
                af[mi][0] = __float_as_uint(Qs[(m0+gid  )*68 + ks+tig  ]);
                af[mi][1] = __float_as_uint(Qs[(m0+gid+8)*68 + ks+tig  ]);
                af[mi][2] = __float_as_uint(Qs[(m0+gid  )*68 + ks+tig+4]);
                af[mi][3] = __float_as_uint(Qs[(m0+gid+8)*68 + ks+tig+4]);
            }
            #pragma unroll
            for (int ni=0;ni<4;++ni) {
                const int n0 = wN + ni*8;
                bf[ni][0] = __float_as_uint(Ks[(n0+gid)*68 + ks+tig  ]);
                bf[ni][1] = __float_as_uint(Ks[(n0+gid)*68 + ks+tig+4]);
            }
            #pragma unroll
            for (int mi=0;mi<4;++mi)
                #pragma unroll
                for (int ni=0;ni<4;++ni)
                    mma8(acc[mi][ni], af[mi], bf[ni]);
        }

        const int ntile = ntile2*2 + j;
        #pragma unroll
        for (int mi=0;mi<4;++mi) {
            const int lr0 = wM + mi*16 + gid;
            const float iv0 = smi[lr0], iv1 = smi[lr0+8];
            const int r0 = rowtile*128 + lr0;
            #pragma unroll
            for (int ni=0;ni<4;++ni) {
                const int c0 = ntile*128 + wN + ni*8 + tig*2;
                float p0 = exp8(acc[mi][ni][0])*iv0;
                float p1 = exp8(acc[mi][ni][1])*iv0;
                float p2 = exp8(acc[mi][ni][2])*iv1;
                float p3 = exp8(acc[mi][ni][3])*iv1;
                stg_cs2(Cp + (size_t)r0*SEQ + c0,     p0, p1);
                stg_cs2(Cp + (size_t)(r0+8)*SEQ + c0, p2, p3);
            }
        }
        // no sync needed between j: buffers disjoint, smi read-only
    }
}

// ---------------------------------------------------------------------------
extern "C" void kernel_launch(void* const* d_in, const int* in_sizes, int n_in,
                              void* d_out, int out_size)
{
    const float* Q  = (const float*)d_in[0];
    const float* K_ = (const float*)d_in[1];
    const float* V  = (const float*)d_in[2];
    const float* Wq = (const float*)d_in[3];
    const float* bq = (const float*)d_in[4];
    const float* Wk = (const float*)d_in[5];
    const float* bk = (const float*)d_in[6];
    const float* Wv = (const float*)d_in[7];
    const float* bv = (const float*)d_in[8];
    const float* Wo = (const float*)d_in[9];
    const float* bo = (const float*)d_in[10];

    float* probs = (float*)d_out;
    float* out   = probs + (size_t)BATCH*HEADS*SEQ*SEQ;

    float *cq,*ck,*cv,*cwq,*cwk,*cwv,*cwo;
    float *gq, *gk, *gv, *gctx, *gi;
    cudaGetSymbolAddress((void**)&cq,  g_cq);
    cudaGetSymbolAddress((void**)&ck,  g_ck);
    cudaGetSymbolAddress((void**)&cv,  g_cv);
    cudaGetSymbolAddress((void**)&cwq, g_cwq);
    cudaGetSymbolAddress((void**)&cwk, g_cwk);
    cudaGetSymbolAddress((void**)&cwv, g_cwv);
    cudaGetSymbolAddress((void**)&cwo, g_cwo);
    cudaGetSymbolAddress((void**)&gq,  g_q);
    cudaGetSymbolAddress((void**)&gk,  g_k);
    cudaGetSymbolAddress((void**)&gv,  g_v);
    cudaGetSymbolAddress((void**)&gctx, g_ctx);
    cudaGetSymbolAddress((void**)&gi,  g_inv);

    const int SM_PROJ  = 18432 * 4;   //  73728 B
    const int SM_FLASH = 44416 * 4;   // 177664 B
    const int SM_PW    = 26240 * 4;   // 104960 B -> occ 2
    cudaFuncSetAttribute(proj_gemm<true>,  cudaFuncAttributeMaxDynamicSharedMemorySize, SM_PROJ);
    cudaFuncSetAttribute(proj_gemm<false>, cudaFuncAttributeMaxDynamicSharedMemorySize, SM_PROJ);
    cudaFuncSetAttribute(flash_fwd,   cudaFuncAttributeMaxDynamicSharedMemorySize, SM_FLASH);
    cudaFuncSetAttribute(probs_write, cudaFuncAttributeMaxDynamicSharedMemorySize, SM_PW);

    const int NBIG = (BATCH*SEQ*DMODEL)/4;
    const int NW   = (DMODEL*DMODEL)/4;

    // 0) tf32 pre-rounding
    cvt_pass<<<dim3(148,3), 256>>>(Q, cq, NBIG, K_, ck, NBIG, V, cv, NBIG, V, cv, 0);
    cvt_pass<<<dim3(64,4),  256>>>(Wq, cwq, NW, Wk, cwk, NW, Wv, cwv, NW, Wo, cwo, NW);

    // 1) Q,K,V projections
    proj_gemm<true><<<dim3(8,32,3), 256, SM_PROJ>>>(cq, ck, cv, cwq, cwk, cwv, bq, bk, bv, gq, gk, gv);

    // 2) flash fwd (unchanged from R14)
    flash_fwd<<<dim3(16,32), 256, SM_FLASH>>>(gq, gk, gv, gi, gctx);

    // 3) probs: 2-ntile CTAs, K double-buffered, streaming stores
    probs_write<<<dim3(8,16,32), 256, SM_PW>>>(gq, gk, gi, probs);

    // 4) output projection
    proj_gemm<false><<<dim3(8,32,1), 256, SM_PROJ>>>(gctx, gctx, gctx, cwo, cwo, cwo, bo, bo, bo, out, out, out);
}

// round 17
// speedup vs baseline: 1.0098x; 1.0098x over previous
#include <cuda_runtime.h>
#include <math.h>
#include <stdint.h>

#define BATCH 2
#define SEQ 2048
#define DMODEL 1024
#define HEADS 16
#define DK 64
#define NROWS (BATCH*HEADS*SEQ)

// tf32-rounded copies of inputs
static __device__ float g_cq[BATCH*SEQ*DMODEL];
static __device__ float g_ck[BATCH*SEQ*DMODEL];
static __device__ float g_cv[BATCH*SEQ*DMODEL];
static __device__ float g_cwq[DMODEL*DMODEL];
static __device__ float g_cwk[DMODEL*DMODEL];
static __device__ float g_cwv[DMODEL*DMODEL];
static __device__ float g_cwo[DMODEL*DMODEL];
// Projected scratch (tf32-rounded), [B,S,D] layout
static __device__ float g_q[BATCH*SEQ*DMODEL];
static __device__ float g_k[BATCH*SEQ*DMODEL];
static __device__ float g_v[BATCH*SEQ*DMODEL];
static __device__ float g_ctx[BATCH*SEQ*DMODEL];
// per-row 1/sum
static __device__ float g_inv[NROWS];

__device__ __forceinline__ float to_tf32(float x) {
    float y;
    asm("cvt.rna.tf32.f32 %0, %1;" : "=f"(y) : "f"(x));
    return y;
}
// exp(x/8) = 2^(x * 0.125*log2(e))
__device__ __forceinline__ float exp8(float x) {
    float y;
    asm("ex2.approx.ftz.f32 %0, %1;" : "=f"(y) : "f"(x * 0.18033688011112042f));
    return y;
}
__device__ __forceinline__ void mma8(float* d, const uint32_t* a, const uint32_t* b) {
    asm volatile(
        "mma.sync.aligned.m16n8k8.row.col.f32.tf32.tf32.f32 "
        "{%0,%1,%2,%3}, {%4,%5,%6,%7}, {%8,%9}, {%0,%1,%2,%3};\n"
        : "+f"(d[0]), "+f"(d[1]), "+f"(d[2]), "+f"(d[3])
        : "r"(a[0]), "r"(a[1]), "r"(a[2]), "r"(a[3]),
          "r"(b[0]), "r"(b[1]));
}
__device__ __forceinline__ void cp16(uint32_t dst_smem, const void* src) {
    asm volatile("cp.async.cg.shared.global [%0], [%1], 16;\n" :: "r"(dst_smem), "l"(src));
}
__device__ __forceinline__ void cp_commit() { asm volatile("cp.async.commit_group;\n"); }
template<int N> __device__ __forceinline__ void cp_wait() {
    asm volatile("cp.async.wait_group %0;\n" :: "n"(N));
}

// ---------------------------------------------------------------------------
__global__ void __launch_bounds__(256)
cvt_pass(const float* s0, float* d0, int n0,
         const float* s1, float* d1, int n1,
         const float* s2, float* d2, int n2,
         const float* s3, float* d3, int n3)
{
    const int z = blockIdx.y;
    const float* s = (z==0)?s0:((z==1)?s1:((z==2)?s2:s3));
    float*       d = (z==0)?d0:((z==1)?d1:((z==2)?d2:d3));
    const int    n = (z==0)?n0:((z==1)?n1:((z==2)?n2:n3));
    for (int i = blockIdx.x*256 + threadIdx.x; i < n; i += gridDim.x*256) {
        float4 x = ((const float4*)s)[i];
        x.x = to_tf32(x.x); x.y = to_tf32(x.y);
        x.z = to_tf32(x.z); x.w = to_tf32(x.w);
        ((float4*)d)[i] = x;
    }
}

// ---------------------------------------------------------------------------
// Projection GEMM: C[4096,1024] = A @ W^T + bias, z selects triple.
// ---------------------------------------------------------------------------
template<bool CVT_OUT>
__global__ void __launch_bounds__(256, 2)
proj_gemm(const float* __restrict__ A0, const float* __restrict__ A1, const float* __restrict__ A2,
          const float* __restrict__ W0, const float* __restrict__ W1, const float* __restrict__ W2,
          const float* __restrict__ B0, const float* __restrict__ B1, const float* __restrict__ B2,
          float* __restrict__ C0, float* __restrict__ C1, float* __restrict__ C2)
{
    extern __shared__ __align__(16) float sm[];
    const int tid = threadIdx.x;
    const int z = blockIdx.z;
    const float* A    = (z==0) ? A0 : ((z==1) ? A1 : A2);
    const float* W    = (z==0) ? W0 : ((z==1) ? W1 : W2);
    const float* bias = (z==0) ? B0 : ((z==1) ? B1 : B2);
    float*       C    = (z==0) ? C0 : ((z==1) ? C1 : C2);
    const int tileN = blockIdx.x * 128;
    const int tileM = blockIdx.y * 128;

    const int warp = tid >> 5, lane = tid & 31, gid = lane >> 2, tig = lane & 3;
    const int wM = (warp & 1) * 64, wN = (warp >> 1) * 32;
    const uint32_t smb = (uint32_t)__cvta_generic_to_shared(sm);

    float acc[4][4][4];
    #pragma unroll
    for (int i=0;i<4;++i)
        #pragma unroll
        for (int j=0;j<4;++j)
            #pragma unroll
            for (int r=0;r<4;++r) acc[i][j][r]=0.f;

    #pragma unroll
    for (int i=0;i<4;++i) {
        int e = tid + i*256, m = e>>3, kq = e&7;
        cp16(smb + (uint32_t)((m*36 + kq*4)*4),          A + (size_t)(tileM+m)*1024 + kq*4);
        cp16(smb + (uint32_t)((9216 + m*36 + kq*4)*4),   W + (size_t)(tileN+m)*1024 + kq*4);
    }
    cp_commit();

    for (int it = 0; it < 32; ++it) {
        const int cur = it & 1;
        if (it < 31) {
            const int nb = cur ^ 1;
            const int k0 = (it+1)*32;
            #pragma unroll
            for (int i=0;i<4;++i) {
                int e = tid + i*256, m = e>>3, kq = e&7;
                cp16(smb + (uint32_t)((nb*4608 + m*36 + kq*4)*4),        A + (size_t)(tileM+m)*1024 + k0 + kq*4);
                cp16(smb + (uint32_t)((9216 + nb*4608 + m*36 + kq*4)*4), W + (size_t)(tileN+m)*1024 + k0 + kq*4);
            }
            cp_commit();
            cp_wait<1>();
        } else {
            cp_wait<0>();
        }
        __syncthreads();

        const float* As = sm + cur*4608;
        const float* Ws = sm + 9216 + cur*4608;
        #pragma unroll
        for (int ks = 0; ks < 32; ks += 8) {
            uint32_t af[4][4], bf[4][2];
            #pragma unroll
            for (int mi=0;mi<4;++mi) {
                const int m0 = wM + mi*16;
                af[mi][0] = __float_as_uint(As[(m0+gid  )*36 + ks+tig  ]);
                af[mi][1] = __float_as_uint(As[(m0+gid+8)*36 + ks+tig  ]);
                af[mi][2] = __float_as_uint(As[(m0+gid  )*36 + ks+tig+4]);
                af[mi][3] = __float_as_uint(As[(m0+gid+8)*36 + ks+tig+4]);
            }
            #pragma unroll
            for (int ni=0;ni<4;++ni) {
                const int n0 = wN + ni*8;
                bf[ni][0] = __float_as_uint(Ws[(n0+gid)*36 + ks+tig  ]);
                bf[ni][1] = __float_as_uint(Ws[(n0+gid)*36 + ks+tig+4]);
            }
            #pragma unroll
            for (int mi=0;mi<4;++mi)
                #pragma unroll
                for (int ni=0;ni<4;++ni)
                    mma8(acc[mi][ni], af[mi], bf[ni]);
        }
        __syncthreads();
    }

    #pragma unroll
    for (int mi=0;mi<4;++mi) {
        const int r0 = tileM + wM + mi*16 + gid;
        #pragma unroll
        for (int ni=0;ni<4;++ni) {
            const int c0 = tileN + wN + ni*8 + tig*2;
            const float b0 = bias[c0], b1 = bias[c0+1];
            float v0 = acc[mi][ni][0]+b0, v1 = acc[mi][ni][1]+b1;
            float v2 = acc[mi][ni][2]+b0, v3 = acc[mi][ni][3]+b1;
            if (CVT_OUT) {
                v0 = to_tf32(v0); v1 = to_tf32(v1);
                v2 = to_tf32(v2); v3 = to_tf32(v3);
            }
            *(float2*)(C + (size_t)r0*1024 + c0)     = make_float2(v0, v1);
            *(float2*)(C + (size_t)(r0+8)*1024 + c0) = make_float2(v2, v3);
        }
    }
}

// ---------------------------------------------------------------------------
// Flash forward (R14, unchanged): warp-specialized producer/consumer.
// ---------------------------------------------------------------------------
__global__ void __launch_bounds__(256, 1)
flash_fwd(const float* __restrict__ q, const float* __restrict__ kmat,
          const float* __restrict__ v, float* __restrict__ ginv,
          float* __restrict__ ctx)
{
    extern __shared__ __align__(16) float sm[];
    float* Qs   = sm;
    float* redf = sm + 44032;
    float* smi  = sm + 44288;

    const int tid = threadIdx.x, rowtile = blockIdx.x, z = blockIdx.y;
    const int b = z >> 4, h = z & 15;
    const float* Qp = q    + ((size_t)b*SEQ + rowtile*128)*DMODEL + h*DK;
    const float* Kp = kmat + (size_t)b*SEQ*DMODEL + h*DK;
    const float* Vp = v    + (size_t)b*SEQ*DMODEL + h*DK;
    const uint32_t smb = (uint32_t)__cvta_generic_to_shared(sm);

    const int warp = tid >> 5, lane = tid & 31, gid = lane >> 2, tig = lane & 3;
    const bool isA = (warp < 4);
    const int wMa = (warp & 1) * 64, wNa = ((warp >> 1) & 1) * 32;
    const int warp_na = (warp >> 1) & 1;
    const int wl = warp & 3;
    const int wMb = (wl & 1) * 64, wNb = (wl >> 1) * 32;

    // prologue: Q (8 f4/thread) + K(0) (4 f4/thread)
    #pragma unroll
    for (int i=0;i<8;++i) {
        int e = tid + i*256, m = e>>4, kq = e&15;
        cp16(smb + (uint32_t)((m*68 + kq*4)*4), Qp + (size_t)m*1024 + kq*4);
    }
    #pragma unroll
    for (int i=0;i<4;++i) {
        int e = tid + i*256, m = e>>4, kq = e&15;
        cp16(smb + (uint32_t)((8704 + m*68 + kq*4)*4), Kp + (size_t)m*1024 + kq*4);
    }
    cp_commit();

    float acc2[4][4][4];   // B ctx accumulator
    #pragma unroll
    for (int i=0;i<4;++i)
        #pragma unroll
        for (int j=0;j<4;++j)
            #pragma unroll
            for (int r=0;r<4;++r) acc2[i][j][r]=0.f;
    float srun[4][2];      // A per-thread row-sum partials
    #pragma unroll
    for (int mi=0;mi<4;++mi) { srun[mi][0]=0.f; srun[mi][1]=0.f; }

    for (int nt = 0; nt < 32; ++nt) {
        const int cur = nt & 1;
        cp_wait<0>();
        __syncthreads();   // K(nt), V(nt-1) landed; Es stable

        // prefetch K(nt+1) -> Ks[nt+1&1], V(nt) -> Vs[nt&1]
        {
            #pragma unroll
            for (int i=0;i<4;++i) {
                int e = tid + i*256, m = e>>4, kq = e&15;
                if (nt < 31)
                    cp16(smb + (uint32_t)((8704 + (cur^1)*4352 + m*68 + kq*4)*4),
                         Kp + (size_t)((nt+1)*64+m)*1024 + kq*4);
                cp16(smb + (uint32_t)((17408 + cur*4608 + m*72 + kq*4)*4),
                     Vp + (size_t)(nt*64+m)*1024 + kq*4);
            }
            cp_commit();
        }

        if (isA) {
            // scores mma: 128x64x64
            const float* Kb = sm + 8704 + cur*4352;
            float acc[4][4][4];
            #pragma unroll
            for (int i=0;i<4;++i)
                #pragma unroll
                for (int j=0;j<4;++j)
                    #pragma unroll
                    for (int r=0;r<4;++r) acc[i][j][r]=0.f;
            #pragma unroll
            for (int ks = 0; ks < 64; ks += 8) {
                uint32_t af[4][4], bf[4][2];
                #pragma unroll
                for (int mi=0;mi<4;++mi) {
                    const int m0 = wMa + mi*16;
                    af[mi][0] = __float_as_uint(Qs[(m0+gid  )*68 + ks+tig  ]);
                    af[mi][1] = __float_as_uint(Qs[(m0+gid+8)*68 + ks+tig  ]);
                    af[mi][2] = __float_as_uint(Qs[(m0+gid  )*68 + ks+tig+4]);
                    af[mi][3] = __float_as_uint(Qs[(m0+gid+8)*68 + ks+tig+4]);
                }
                #pragma unroll
                for (int ni=0;ni<4;++ni) {
                    const int n0 = wNa + ni*8;
                    bf[ni][0] = __float_as_uint(Kb[(n0+gid)*68 + ks+tig  ]);
                    bf[ni][1] = __float_as_uint(Kb[(n0+gid)*68 + ks+tig+4]);
                }
                #pragma unroll
                for (int mi=0;mi<4;++mi)
                    #pragma unroll
                    for (int ni=0;ni<4;++ni)
                        mma8(acc[mi][ni], af[mi], bf[ni]);
            }

            // e = tf32(exp8(s)); per-thread partial sums (no shfl in loop)
            #pragma unroll
            for (int mi=0;mi<4;++mi) {
                #pragma unroll
                for (int hf=0;hf<2;++hf) {
                    float s = 0.f;
                    #pragma unroll
                    for (int ni=0;ni<4;++ni) {
                        float e0 = to_tf32(exp8(acc[mi][ni][hf*2]));
                        float e1 = to_tf32(exp8(acc[mi][ni][hf*2+1]));
                        acc[mi][ni][hf*2]   = e0;
                        acc[mi][ni][hf*2+1] = e1;
                        s += e0 + e1;
                    }
                    srun[mi][hf] += s;
                }
            }
            float* Eb = sm + 26624 + cur*8704;
            #pragma unroll
            for (int mi=0;mi<4;++mi) {
                const int r0 = wMa + mi*16 + gid;
                #pragma unroll
                for (int ni=0;ni<4;++ni) {
                    const int c0 = wNa + ni*8 + tig*2;
                    *(float2*)(Eb + (r0  )*68 + c0) = make_float2(acc[mi][ni][0], acc[mi][ni][1]);
                    *(float2*)(Eb + (r0+8)*68 + c0) = make_float2(acc[mi][ni][2], acc[mi][ni][3]);
                }
            }
        } else if (nt > 0) {
            // ctx mma: acc2 += Es[(nt-1)&1] @ Vs[(nt-1)&1]
            const float* Eb = sm + 26624 + (cur^1)*8704;
            const float* Vb = sm + 17408 + (cur^1)*4608;
            #pragma unroll
            for (int ks = 0; ks < 64; ks += 8) {
                uint32_t af[4][4], bf[4][2];
                #pragma unroll
                for (int mi=0;mi<4;++mi) {
                    const int m0 = wMb + mi*16;
                    af[mi][0] = __float_as_uint(Eb[(m0+gid  )*68 + ks+tig  ]);
                    af[mi][1] = __float_as_uint(Eb[(m0+gid+8)*68 + ks+tig  ]);
                    af[mi][2] = __float_as_uint(Eb[(m0+gid  )*68 + ks+tig+4]);
                    af[mi][3] = __float_as_uint(Eb[(m0+gid+8)*68 + ks+tig+4]);
                }
                #pragma unroll
                for (int ni=0;ni<4;++ni) {
                    const int n0 = wNb + ni*8;
                    bf[ni][0] = __float_as_uint(Vb[(ks+tig  )*72 + n0+gid]);
                    bf[ni][1] = __float_as_uint(Vb[(ks+tig+4)*72 + n0+gid]);
                }
                #pragma unroll
                for (int mi=0;mi<4;++mi)
                    #pragma unroll
                    for (int ni=0;ni<4;++ni)
                        mma8(acc2[mi][ni], af[mi], bf[ni]);
            }
        }
        __syncthreads();
    }

    // tail: B processes tile 31; A reduces (deferred shuffles) + publishes sums
    cp_wait<0>();
    __syncthreads();
    if (isA) {
        #pragma unroll
        for (int mi=0;mi<4;++mi) {
            #pragma unroll
            for (int hf=0;hf<2;++hf) {
                float s = srun[mi][hf];
                s += __shfl_xor_sync(0xffffffffu, s, 1);
                s += __shfl_xor_sync(0xffffffffu, s, 2);
                if (tig == 0)
                    redf[warp_na*128 + wMa + mi*16 + gid + hf*8] = s;
            }
        }
    } else {
        const float* Eb = sm + 26624 + 1*8704;   // Es[31&1]
        const float* Vb = sm + 17408 + 1*4608;   // Vs[31&1]
        #pragma unroll
        for (int ks = 0; ks < 64; ks += 8) {
            uint32_t af[4][4], bf[4][2];
            #pragma unroll
            for (int mi=0;mi<4;++mi) {
                const int m0 = wMb + mi*16;
                af[mi][0] = __float_as_uint(Eb[(m0+gid  )*68 + ks+tig  ]);
                af[mi][1] = __float_as_uint(Eb[(m0+gid+8)*68 + ks+tig  ]);
                af[mi][2] = __float_as_uint(Eb[(m0+gid  )*68 + ks+tig+4]);
                af[mi][3] = __float_as_uint(Eb[(m0+gid+8)*68 + ks+tig+4]);
            }
            #pragma unroll
            for (int ni=0;ni<4;++ni) {
                const int n0 = wNb + ni*8;
                bf[ni][0] = __float_as_uint(Vb[(ks+tig  )*72 + n0+gid]);
                bf[ni][1] = __float_as_uint(Vb[(ks+tig+4)*72 + n0+gid]);
            }
            #pragma unroll
            for (int mi=0;mi<4;++mi)
                #pragma unroll
                for (int ni=0;ni<4;++ni)
                    mma8(acc2[mi][ni], af[mi], bf[ni]);
        }
    }
    __syncthreads();
    if (tid < 128) {
        float S = redf[tid] + redf[128+tid];
        float iv = 1.f / S;
        smi[tid] = iv;
        ginv[(size_t)z*SEQ + rowtile*128 + tid] = iv;
    }
    __syncthreads();

    // B epilogue: scale by inv[row], write ctx
    if (!isA) {
        float* Cp = ctx + ((size_t)b*SEQ + rowtile*128)*DMODEL + h*DK;
        #pragma unroll
        for (int mi=0;mi<4;++mi) {
            const int r0 = wMb + mi*16 + gid;
            const float iv0 = smi[r0], iv1 = smi[r0+8];
            #pragma unroll
            for (int ni=0;ni<4;++ni) {
                const int c0 = wNb + ni*8 + tig*2;
                *(float2*)(Cp + (size_t)r0*1024 + c0)
                    = make_float2(to_tf32(acc2[mi][ni][0]*iv0), to_tf32(acc2[mi][ni][1]*iv0));
                *(float2*)(Cp + (size_t)(r0+8)*1024 + c0)
                    = make_float2(to_tf32(acc2[mi][ni][2]*iv1), to_tf32(acc2[mi][ni][3]*iv1));
            }
        }
    }
}

// ---------------------------------------------------------------------------
// Probs writer (R14 config): recompute scores tile, p = exp8(s)*inv[row], STG.
// smem (words): Qs[128][68]=0, Ks[128][68]=8704, inv[128]=17408. 70144 B.
// ---------------------------------------------------------------------------
__global__ void __launch_bounds__(256, 2)
probs_write(const float* __restrict__ q, const float* __restrict__ kmat,
            const float* __restrict__ ginv, float* __restrict__ probs)
{
    extern __shared__ __align__(16) float sm[];
    float* smi = sm + 17408;
    const int tid = threadIdx.x;
    const int ntile = blockIdx.x, rowtile = blockIdx.y, z = blockIdx.z;
    const int b = z >> 4, h = z & 15;

    const float* Qp = q    + ((size_t)b*SEQ + rowtile*128)*DMODEL + h*DK;
    const float* Kp = kmat + ((size_t)b*SEQ + ntile*128)*DMODEL + h*DK;
    const uint32_t smb = (uint32_t)__cvta_generic_to_shared(sm);

    #pragma unroll
    for (int i=0;i<8;++i) {
        int e = tid + i*256, m = e>>4, kq = e&15;
        cp16(smb + (uint32_t)((m*68 + kq*4)*4),          Qp + (size_t)m*1024 + kq*4);
        cp16(smb + (uint32_t)((8704 + m*68 + kq*4)*4),   Kp + (size_t)m*1024 + kq*4);
    }
    cp_commit();
    if (tid < 128) smi[tid] = ginv[(size_t)z*SEQ + rowtile*128 + tid];
    cp_wait<0>();
    __syncthreads();

    const int warp = tid >> 5, lane = tid & 31, gid = lane >> 2, tig = lane & 3;
    const int wM = (warp & 1) * 64, wN = (warp >> 1) * 32;

    float acc[4][4][4];
    #pragma unroll
    for (int i=0;i<4;++i)
        #pragma unroll
        for (int j=0;j<4;++j)
            #pragma unroll
            for (int r=0;r<4;++r) acc[i][j][r]=0.f;

    const float* Qs = sm;
    const float* Ks = sm + 8704;
    #pragma unroll
    for (int ks = 0; ks < 64; ks += 8) {
        uint32_t af[4][4], bf[4][2];
        #pragma unroll
        for (int mi=0;mi<4;++mi) {
            const int m0 = wM + mi*16;
            af[mi][0] = __float_as_uint(Qs[(m0+gid  )*68 + ks+tig  ]);
            af[mi][1] = __float_as_uint(Qs[(m0+gid+8)*68 + ks+tig  ]);
            af[mi][2] = __float_as_uint(Qs[(m0+gid  )*68 + ks+tig+4]);
            af[mi][3] = __float_as_uint(Qs[(m0+gid+8)*68 + ks+tig+4]);
        }
        #pragma unroll
        for (int ni=0;ni<4;++ni) {
            const int n0 = wN + ni*8;
            bf[ni][0] = __float_as_uint(Ks[(n0+gid)*68 + ks+tig  ]);
            bf[ni][1] = __float_as_uint(Ks[(n0+gid)*68 + ks+tig+4]);
        }
        #pragma unroll
        for (int mi=0;mi<4;++mi)
            #pragma unroll
            for (int ni=0;ni<4;++ni)
                mma8(acc[mi][ni], af[mi], bf[ni]);
    }

    float* Cp = probs + (size_t)z*SEQ*SEQ;
    #pragma unroll
    for (int mi=0;mi<4;++mi) {
        const int lr0 = wM + mi*16 + gid;
        const float iv0 = smi[lr0], iv1 = smi[lr0+8];
        const int r0 = rowtile*128 + lr0;
        #pragma unroll
        for (int ni=0;ni<4;++ni) {
            const int c0 = ntile*128 + wN + ni*8 + tig*2;
            float p0 = exp8(acc[mi][ni][0])*iv0;
            float p1 = exp8(acc[mi][ni][1])*iv0;
            float p2 = exp8(acc[mi][ni][2])*iv1;
            float p3 = exp8(acc[mi][ni][3])*iv1;
            *(float2*)(Cp + (size_t)r0*SEQ + c0)     = make_float2(p0, p1);
            *(float2*)(Cp + (size_t)(r0+8)*SEQ + c0) = make_float2(p2, p3);
        }
    }
}

// ---------------------------------------------------------------------------
extern "C" void kernel_launch(void* const* d_in, const int* in_sizes, int n_in,
                              void* d_out, int out_size)
{
    const float* Q  = (const float*)d_in[0];
    const float* K_ = (const float*)d_in[1];
    const float* V  = (const float*)d_in[2];
    const float* Wq = (const float*)d_in[3];
    const float* bq = (const float*)d_in[4];
    const float* Wk = (const float*)d_in[5];
    const float* bk = (const float*)d_in[6];
    const float* Wv = (const float*)d_in[7];
    const float* bv = (const float*)d_in[8];
    const float* Wo = (const float*)d_in[9];
    const float* bo = (const float*)d_in[10];

    float* probs = (float*)d_out;
    float* out   = probs + (size_t)BATCH*HEADS*SEQ*SEQ;

    float *cq,*ck,*cv,*cwq,*cwk,*cwv,*cwo;
    float *gq, *gk, *gv, *gctx, *gi;
    cudaGetSymbolAddress((void**)&cq,  g_cq);
    cudaGetSymbolAddress((void**)&ck,  g_ck);
    cudaGetSymbolAddress((void**)&cv,  g_cv);
    cudaGetSymbolAddress((void**)&cwq, g_cwq);
    cudaGetSymbolAddress((void**)&cwk, g_cwk);
    cudaGetSymbolAddress((void**)&cwv, g_cwv);
    cudaGetSymbolAddress((void**)&cwo, g_cwo);
    cudaGetSymbolAddress((void**)&gq,  g_q);
    cudaGetSymbolAddress((void**)&gk,  g_k);
    cudaGetSymbolAddress((void**)&gv,  g_v);
    cudaGetSymbolAddress((void**)&gctx, g_ctx);
    cudaGetSymbolAddress((void**)&gi,  g_inv);

    const int SM_PROJ  = 18432 * 4;   //  73728 B
    const int SM_FLASH = 44416 * 4;   // 177664 B
    const int SM_PW    = 17536 * 4;   //  70144 B
    cudaFuncSetAttribute(proj_gemm<true>,  cudaFuncAttributeMaxDynamicSharedMemorySize, SM_PROJ);
    cudaFuncSetAttribute(proj_gemm<false>, cudaFuncAttributeMaxDynamicSharedMemorySize, SM_PROJ);
    cudaFuncSetAttribute(flash_fwd,   cudaFuncAttributeMaxDynamicSharedMemorySize, SM_FLASH);
    cudaFuncSetAttribute(probs_write, cudaFuncAttributeMaxDynamicSharedMemorySize, SM_PW);

    const int NBIG = (BATCH*SEQ*DMODEL)/4;
    const int NW   = (DMODEL*DMODEL)/4;

    // 0) tf32 pre-rounding
    cvt_pass<<<dim3(148,3), 256>>>(Q, cq, NBIG, K_, ck, NBIG, V, cv, NBIG, V, cv, 0);
    cvt_pass<<<dim3(64,4),  256>>>(Wq, cwq, NW, Wk, cwk, NW, Wv, cwv, NW, Wo, cwo, NW);

    // 1) Q,K,V projections
    proj_gemm<true><<<dim3(8,32,3), 256, SM_PROJ>>>(cq, ck, cv, cwq, cwk, cwv, bq, bk, bv, gq, gk, gv);

    // 2) flash fwd (R14)
    flash_fwd<<<dim3(16,32), 256, SM_FLASH>>>(gq, gk, gv, gi, gctx);

    // 3)+4) probs_write (side stream) overlapped with output projection (main).
    // Fork-join pattern; stream/event creation is host-side only and happens
    // during capture, not during timed graph replays.
    cudaStream_t s2;
    cudaEvent_t evFork, evJoin;
    cudaStreamCreateWithFlags(&s2, cudaStreamNonBlocking);
    cudaEventCreateWithFlags(&evFork, cudaEventDisableTiming);
    cudaEventCreateWithFlags(&evJoin, cudaEventDisableTiming);

    cudaEventRecord(evFork, 0);
    cudaStreamWaitEvent(s2, evFork, 0);

    probs_write<<<dim3(16,16,32), 256, SM_PW, s2>>>(gq, gk, gi, probs);
    proj_gemm<false><<<dim3(8,32,1), 256, SM_PROJ>>>(gctx, gctx, gctx, cwo, cwo, cwo, bo, bo, bo, out, out, out);

    cudaEventRecord(evJoin, s2);
    cudaStreamWaitEvent(0, evJoin, 0);

    cudaEventDestroy(evFork);
    cudaEventDestroy(evJoin);
    cudaStreamDestroy(s2);
}